// round 3
// baseline (speedup 1.0000x reference)
#include <cuda_runtime.h>
#include <cstdint>

// Problem constants (fixed instance)
#define DM   128      // model dim
#define HH   8        // heads
#define DHD  16       // head dim
#define MV   3        // views
#define MAXN 100000
#define MAXE 1600000

typedef unsigned long long ull;

// ---------------- scratch (static __device__ — no allocations) ----------------
__device__ float g_q[(size_t)MAXN * DM];
__device__ float g_k[(size_t)MAXN * DM];
__device__ float g_v[(size_t)MAXN * DM];
__device__ float g_w[(size_t)MAXE * HH];     // per-edge unnormalized softmax weights
__device__ int   g_count[MAXN];
__device__ int   g_rowptr[MAXN + 1];
__device__ int   g_rowfill[MAXN];
__device__ int2  g_elist[MAXE];              // (edge_id, src)

// ---------------- packed f32x2 helpers ----------------
__device__ __forceinline__ ull fma2(ull a, ull b, ull c) {
    ull d;
    asm("fma.rn.f32x2 %0, %1, %2, %3;" : "=l"(d) : "l"(a), "l"(b), "l"(c));
    return d;
}
__device__ __forceinline__ ull bcast2(float x) {
    ull d;
    asm("mov.b64 %0, {%1, %1};" : "=l"(d) : "r"(__float_as_uint(x)));
    return d;
}

// ---------------- CSR build ----------------
__global__ void zero_count_kernel(int n) {
    int i = blockIdx.x * blockDim.x + threadIdx.x;
    if (i < n) g_count[i] = 0;
}

__global__ void hist_kernel(const int* __restrict__ dst, int e) {
    for (int i = blockIdx.x * blockDim.x + threadIdx.x; i < e; i += gridDim.x * blockDim.x)
        atomicAdd(&g_count[dst[i]], 1);
}

__global__ void scan_count_kernel(int n) {
    __shared__ int s_wsum[32];
    __shared__ int s_carry;
    const int tid = threadIdx.x;
    const int lane = tid & 31, wid = tid >> 5;
    if (tid == 0) s_carry = 0;
    __syncthreads();
    for (int base = 0; base < n; base += 1024) {
        int i = base + tid;
        int v = (i < n) ? g_count[i] : 0;
        int x = v;
#pragma unroll
        for (int o = 1; o < 32; o <<= 1) {
            int t = __shfl_up_sync(0xffffffffu, x, o);
            if (lane >= o) x += t;
        }
        if (lane == 31) s_wsum[wid] = x;
        __syncthreads();
        if (wid == 0) {
            int ws = s_wsum[lane];
#pragma unroll
            for (int o = 1; o < 32; o <<= 1) {
                int t = __shfl_up_sync(0xffffffffu, ws, o);
                if (lane >= o) ws += t;
            }
            s_wsum[lane] = ws;
        }
        __syncthreads();
        int carry = s_carry;
        int woff = wid ? s_wsum[wid - 1] : 0;
        int excl = carry + woff + (x - v);
        if (i < n) { g_rowptr[i] = excl; g_rowfill[i] = excl; }
        int tile_total = s_wsum[31];
        __syncthreads();
        if (tid == 0) s_carry = carry + tile_total;
        __syncthreads();
    }
    if (tid == 0) g_rowptr[n] = s_carry;
}

__global__ void scatter_kernel(const int* __restrict__ src, const int* __restrict__ dst, int e) {
    for (int i = blockIdx.x * blockDim.x + threadIdx.x; i < e; i += gridDim.x * blockDim.x) {
        int d = dst[i];
        int pos = atomicAdd(&g_rowfill[d], 1);
        g_elist[pos] = make_int2(i, src[i]);
    }
}

// ---------------- fused QKV projection (fp32, packed f32x2 FMA) ----------------
// Block: 256 threads. 32 rows per block. thread = (cp in [0,64), rg in [0,4)).
// Each thread: 8 rows x 2 cols x 3 mats accumulators as f32x2.
__global__ __launch_bounds__(256) void qkv_kernel(
    const float* __restrict__ x,
    const float* __restrict__ Wq, const float* __restrict__ bqv,
    const float* __restrict__ Wk, const float* __restrict__ bkv,
    const float* __restrict__ Wv, const float* __restrict__ bvv,
    int n)
{
    __shared__ float sx[32][DM];  // 16KB
    const int row0 = blockIdx.x * 32;

    // load x tile (zero-pad OOB rows)
    for (int t = threadIdx.x; t < 32 * 32; t += 256) {
        int r = t >> 5, c4 = t & 31;
        int row = row0 + r;
        float4 xv = make_float4(0.f, 0.f, 0.f, 0.f);
        if (row < n) xv = *(const float4*)(x + (size_t)row * DM + c4 * 4);
        *(float4*)(&sx[r][c4 * 4]) = xv;
    }
    __syncthreads();

    const int cp = threadIdx.x & 63;   // column-pair 0..63
    const int rg = threadIdx.x >> 6;   // row group 0..3
    const int c  = cp * 2;

    const ull* wq8 = reinterpret_cast<const ull*>(Wq) + cp;
    const ull* wk8 = reinterpret_cast<const ull*>(Wk) + cp;
    const ull* wv8 = reinterpret_cast<const ull*>(Wv) + cp;

    ull bq2 = reinterpret_cast<const ull*>(bqv)[cp];
    ull bk2 = reinterpret_cast<const ull*>(bkv)[cp];
    ull bv2 = reinterpret_cast<const ull*>(bvv)[cp];

    ull aq[8], ak[8], av[8];
#pragma unroll
    for (int r = 0; r < 8; r++) { aq[r] = bq2; ak[r] = bk2; av[r] = bv2; }

#pragma unroll 8
    for (int d = 0; d < DM; d++) {
        ull wq = wq8[(size_t)d * 64];
        ull wk = wk8[(size_t)d * 64];
        ull wv = wv8[(size_t)d * 64];
#pragma unroll
        for (int r = 0; r < 8; r++) {
            ull x2 = bcast2(sx[rg * 8 + r][d]);
            aq[r] = fma2(x2, wq, aq[r]);
            ak[r] = fma2(x2, wk, ak[r]);
            av[r] = fma2(x2, wv, av[r]);
        }
    }

#pragma unroll
    for (int r = 0; r < 8; r++) {
        int row = row0 + rg * 8 + r;
        if (row < n) {
            *(ull*)(g_q + (size_t)row * DM + c) = aq[r];
            *(ull*)(g_k + (size_t)row * DM + c) = ak[r];
            *(ull*)(g_v + (size_t)row * DM + c) = av[r];
        }
    }
}

// ---------------- fused node pass: scores + softmax + aggregation ----------------
// One warp per node. Lane l owns feature slots [4l, 4l+4) -> head h = l>>2.
__global__ __launch_bounds__(256) void node_kernel(
    const float* __restrict__ pi,
    const float* __restrict__ view_w,
    float* __restrict__ out_states,   // [N, 128]
    float* __restrict__ out_attn,     // [E, 8]
    int n)
{
    const int gw = blockIdx.x * (blockDim.x >> 5) + (threadIdx.x >> 5);
    if (gw >= n) return;
    const int nd = gw;
    const int lane = threadIdx.x & 31;
    const unsigned FULL = 0xffffffffu;

    const int beg = g_rowptr[nd];
    const int end = g_rowptr[nd + 1];

    // q row for this node (lane holds 4 floats of head lane>>2)
    const float4 qv = *(const float4*)(g_q + (size_t)nd * DM + lane * 4);
    const int h = lane >> 2;
    const float pi0 = pi[(size_t)nd * (HH * MV) + h * MV + 0];
    const float pi1 = pi[(size_t)nd * (HH * MV) + h * MV + 1];
    const float pi2 = pi[(size_t)nd * (HH * MV) + h * MV + 2];

    float ssum = 0.f;

    // pass 1: per-edge weights + per-head sums (in registers)
    for (int i = beg; i < end; i++) {
        int2 es = g_elist[i];
        int e = es.x, s = es.y;
        float4 kv = *(const float4*)(g_k + (size_t)s * DM + lane * 4);
        float p = qv.x * kv.x + qv.y * kv.y + qv.z * kv.z + qv.w * kv.w;
        p += __shfl_xor_sync(FULL, p, 1);
        p += __shfl_xor_sync(FULL, p, 2);           // all 4 lanes of group hold head dot
        float raw = p * 0.25f;                       // / sqrt(16)
        const float* vw = view_w + (size_t)e * MV;
        float mix = pi0 * vw[0] + pi1 * vw[1] + pi2 * vw[2];
        float w = (mix > 0.f) ? __expf(raw) * fmaxf(mix, 1e-8f) : 0.f;
        ssum += w;                                   // replicated within 4-lane group
        float wl = __shfl_sync(FULL, w, (lane & 7) * 4);
        if (lane < 8) g_w[(size_t)e * HH + lane] = wl;
    }

    const float inv = 1.f / fmaxf(ssum, 1e-8f);
    const float inv_h = __shfl_sync(FULL, inv, (lane & 7) * 4);  // lanes 0..7: per-head 1/sum

    float4 acc = make_float4(0.f, 0.f, 0.f, 0.f);

    // pass 2: attention + weighted V aggregation (register accumulate, no atomics)
    for (int i = beg; i < end; i++) {
        int2 es = g_elist[i];
        int e = es.x, s = es.y;
        float a = 0.f;
        if (lane < 8) {
            float wl = g_w[(size_t)e * HH + lane];
            a = wl * inv_h;
            out_attn[(size_t)e * HH + lane] = a;
        }
        float ah = __shfl_sync(FULL, a, lane >> 2);
        float4 vv = *(const float4*)(g_v + (size_t)s * DM + lane * 4);
        acc.x += vv.x * ah;
        acc.y += vv.y * ah;
        acc.z += vv.z * ah;
        acc.w += vv.w * ah;
    }

    *(float4*)(out_states + (size_t)nd * DM + lane * 4) = acc;
}

// ---------------- launch ----------------
extern "C" void kernel_launch(void* const* d_in, const int* in_sizes, int n_in,
                              void* d_out, int out_size)
{
    const float* x   = (const float*)d_in[0];
    const float* pi  = (const float*)d_in[1];
    const float* vw  = (const float*)d_in[2];
    const float* Wq  = (const float*)d_in[3];
    const float* bq  = (const float*)d_in[4];
    const float* Wk  = (const float*)d_in[5];
    const float* bk  = (const float*)d_in[6];
    const float* Wv  = (const float*)d_in[7];
    const float* bv  = (const float*)d_in[8];
    const int*   src = (const int*)d_in[9];
    const int*   dst = (const int*)d_in[10];

    const int n = in_sizes[0] / DM;    // nodes
    const int e = in_sizes[10];        // edges

    float* out  = (float*)d_out;
    float* attn = out + (size_t)n * DM;

    int gb = (e + 255) / 256;
    if (gb > 4096) gb = 4096;

    // QKV projection (independent of CSR build)
    qkv_kernel<<<(n + 31) / 32, 256>>>(x, Wq, bq, Wk, bk, Wv, bv, n);

    // CSR by dst
    zero_count_kernel<<<(n + 255) / 256, 256>>>(n);
    hist_kernel<<<gb, 256>>>(dst, e);
    scan_count_kernel<<<1, 1024>>>(n);
    scatter_kernel<<<gb, 256>>>(src, dst, e);

    // fused scores + softmax + aggregation
    node_kernel<<<(n + 7) / 8, 256>>>(pi, vw, out, attn, n);
}

// round 4
// speedup vs baseline: 1.2406x; 1.2406x over previous
#include <cuda_runtime.h>
#include <cuda_fp16.h>
#include <cstdint>

// Problem constants (fixed instance)
#define DM   128      // model dim
#define HH   8        // heads
#define DHD  16       // head dim
#define MV   3        // views
#define MAXN 100000
#define MAXE 1600000

typedef unsigned long long ull;

// ---------------- scratch (static __device__ — no allocations) ----------------
__device__ float  g_q[(size_t)MAXN * DM];
__device__ float  g_k[(size_t)MAXN * DM];
__device__ __half g_vh[(size_t)MAXN * DM];   // V stored fp16 (read-only gather)
__device__ int    g_count[MAXN];
__device__ int    g_rowptr[MAXN + 1];
__device__ int    g_rowfill[MAXN];
__device__ int    g_bsum[128];
__device__ int    g_boff[128];
__device__ int2   g_elist[MAXE];             // (edge_id, src)

// ---------------- packed f32x2 helpers ----------------
__device__ __forceinline__ ull fma2(ull a, ull b, ull c) {
    ull d;
    asm("fma.rn.f32x2 %0, %1, %2, %3;" : "=l"(d) : "l"(a), "l"(b), "l"(c));
    return d;
}
__device__ __forceinline__ ull bcast2(float x) {
    ull d;
    asm("mov.b64 %0, {%1, %1};" : "=l"(d) : "r"(__float_as_uint(x)));
    return d;
}

// ---------------- CSR build ----------------
__global__ void zero_count_kernel(int n) {
    int i = blockIdx.x * blockDim.x + threadIdx.x;
    if (i < n) g_count[i] = 0;
}

__global__ void hist_kernel(const int* __restrict__ dst, int e) {
    for (int i = blockIdx.x * blockDim.x + threadIdx.x; i < e; i += gridDim.x * blockDim.x)
        atomicAdd(&g_count[dst[i]], 1);
}

// per-1024-chunk exclusive scan; block totals to g_bsum
__global__ __launch_bounds__(1024) void blockscan_kernel(int n) {
    __shared__ int s_wsum[32];
    const int tid = threadIdx.x;
    const int lane = tid & 31, wid = tid >> 5;
    const int i = blockIdx.x * 1024 + tid;
    int v = (i < n) ? g_count[i] : 0;
    int x = v;
#pragma unroll
    for (int o = 1; o < 32; o <<= 1) {
        int t = __shfl_up_sync(0xffffffffu, x, o);
        if (lane >= o) x += t;
    }
    if (lane == 31) s_wsum[wid] = x;
    __syncthreads();
    if (wid == 0) {
        int ws = s_wsum[lane];
#pragma unroll
        for (int o = 1; o < 32; o <<= 1) {
            int t = __shfl_up_sync(0xffffffffu, ws, o);
            if (lane >= o) ws += t;
        }
        s_wsum[lane] = ws;
    }
    __syncthreads();
    int excl = (wid ? s_wsum[wid - 1] : 0) + (x - v);
    if (i < n) g_rowptr[i] = excl;
    if (tid == 0) g_bsum[blockIdx.x] = s_wsum[31];
}

// scan the (<=128) block totals on one warp; also writes rowptr[n]
__global__ void bsumscan_kernel(int nb, int n) {
    const int lane = threadIdx.x;
    int carry = 0;
    for (int base = 0; base < nb; base += 32) {
        int idx = base + lane;
        int v = (idx < nb) ? g_bsum[idx] : 0;
        int x = v;
#pragma unroll
        for (int o = 1; o < 32; o <<= 1) {
            int t = __shfl_up_sync(0xffffffffu, x, o);
            if (lane >= o) x += t;
        }
        if (idx < nb) g_boff[idx] = carry + (x - v);
        carry += __shfl_sync(0xffffffffu, x, 31);
    }
    if (lane == 0) g_rowptr[n] = carry;
}

__global__ void addoff_kernel(int n) {
    int i = blockIdx.x * blockDim.x + threadIdx.x;
    if (i < n) {
        int r = g_rowptr[i] + g_boff[i >> 10];
        g_rowptr[i] = r;
        g_rowfill[i] = r;
    }
}

__global__ void scatter_kernel(const int* __restrict__ src, const int* __restrict__ dst, int e) {
    for (int i = blockIdx.x * blockDim.x + threadIdx.x; i < e; i += gridDim.x * blockDim.x) {
        int d = dst[i];
        int pos = atomicAdd(&g_rowfill[d], 1);
        g_elist[pos] = make_int2(i, src[i]);
    }
}

// ---------------- fused QKV projection (fp32 math, packed f32x2 FMA) ----------------
// Block: 256 threads, 32 rows. thread = (cp in [0,64), rg in [0,4)); 8 rows x 2 cols x 3 mats.
// Q,K written fp32; V written fp16.
__global__ __launch_bounds__(256) void qkv_kernel(
    const float* __restrict__ x,
    const float* __restrict__ Wq, const float* __restrict__ bqv,
    const float* __restrict__ Wk, const float* __restrict__ bkv,
    const float* __restrict__ Wv, const float* __restrict__ bvv,
    int n)
{
    __shared__ float sx[32][DM];  // 16KB
    const int row0 = blockIdx.x * 32;

    for (int t = threadIdx.x; t < 32 * 32; t += 256) {
        int r = t >> 5, c4 = t & 31;
        int row = row0 + r;
        float4 xv = make_float4(0.f, 0.f, 0.f, 0.f);
        if (row < n) xv = *(const float4*)(x + (size_t)row * DM + c4 * 4);
        *(float4*)(&sx[r][c4 * 4]) = xv;
    }
    __syncthreads();

    const int cp = threadIdx.x & 63;
    const int rg = threadIdx.x >> 6;
    const int c  = cp * 2;

    const ull* wq8 = reinterpret_cast<const ull*>(Wq) + cp;
    const ull* wk8 = reinterpret_cast<const ull*>(Wk) + cp;
    const ull* wv8 = reinterpret_cast<const ull*>(Wv) + cp;

    ull bq2 = reinterpret_cast<const ull*>(bqv)[cp];
    ull bk2 = reinterpret_cast<const ull*>(bkv)[cp];
    ull bv2 = reinterpret_cast<const ull*>(bvv)[cp];

    ull aq[8], ak[8], av[8];
#pragma unroll
    for (int r = 0; r < 8; r++) { aq[r] = bq2; ak[r] = bk2; av[r] = bv2; }

#pragma unroll 8
    for (int d = 0; d < DM; d++) {
        ull wq = wq8[(size_t)d * 64];
        ull wk = wk8[(size_t)d * 64];
        ull wv = wv8[(size_t)d * 64];
#pragma unroll
        for (int r = 0; r < 8; r++) {
            ull x2 = bcast2(sx[rg * 8 + r][d]);
            aq[r] = fma2(x2, wq, aq[r]);
            ak[r] = fma2(x2, wk, ak[r]);
            av[r] = fma2(x2, wv, av[r]);
        }
    }

#pragma unroll
    for (int r = 0; r < 8; r++) {
        int row = row0 + rg * 8 + r;
        if (row < n) {
            *(ull*)(g_q + (size_t)row * DM + c) = aq[r];
            *(ull*)(g_k + (size_t)row * DM + c) = ak[r];
            float2 vf;
            vf.x = __uint_as_float((unsigned)(av[r] & 0xffffffffu));
            vf.y = __uint_as_float((unsigned)(av[r] >> 32));
            *(__half2*)(g_vh + (size_t)row * DM + c) = __float22half2_rn(vf);
        }
    }
}

// ---------------- fused node pass: scores + softmax + aggregation ----------------
// One warp per node. Lane l owns feature slots [4l,4l+4) -> head h = l>>2.
__global__ __launch_bounds__(256) void node_kernel(
    const float* __restrict__ pi,
    const float* __restrict__ view_w,
    float* __restrict__ out_states,   // [N, 128]
    float* __restrict__ out_attn,     // [E, 8]
    int n)
{
    const int nd = blockIdx.x * (blockDim.x >> 5) + (threadIdx.x >> 5);
    if (nd >= n) return;
    const int lane = threadIdx.x & 31;
    const unsigned FULL = 0xffffffffu;

    const int beg = g_rowptr[nd];
    const int end = g_rowptr[nd + 1];

    const float4 qv = *(const float4*)(g_q + (size_t)nd * DM + lane * 4);
    const int h = lane >> 2;
    const float* pip = pi + (size_t)nd * (HH * MV) + h * MV;
    const float pi0 = pip[0], pi1 = pip[1], pi2 = pip[2];

    float ssum = 0.f;

    // pass 1: per-edge unnormalized weights (w = exp(raw)*mix), prefetch elist
    int2 es = (beg < end) ? g_elist[beg] : make_int2(0, 0);
    for (int i = beg; i < end; i++) {
        int2 cur = es;
        if (i + 1 < end) es = g_elist[i + 1];
        const float4 kv = *(const float4*)(g_k + (size_t)cur.y * DM + lane * 4);
        const float* vw = view_w + (size_t)cur.x * MV;
        float mix = pi0 * vw[0] + pi1 * vw[1] + pi2 * vw[2];
        float p = qv.x * kv.x + qv.y * kv.y + qv.z * kv.z + qv.w * kv.w;
        p += __shfl_xor_sync(FULL, p, 1);
        p += __shfl_xor_sync(FULL, p, 2);       // 4-lane group holds head dot
        float w = (mix > 0.f) ? __expf(p * 0.25f) * fmaxf(mix, 1e-8f) : 0.f;
        ssum += w;                               // replicated within group
        float wl = __shfl_sync(FULL, w, (lane & 7) * 4);
        if (lane < 8) out_attn[(size_t)cur.x * HH + lane] = wl;
    }

    const float inv = 1.f / fmaxf(ssum, 1e-8f);
    const float inv_h = __shfl_sync(FULL, inv, (lane & 7) * 4);

    float4 acc = make_float4(0.f, 0.f, 0.f, 0.f);

    // pass 2: normalize attn in place + weighted V (fp16) aggregation
    es = (beg < end) ? g_elist[beg] : make_int2(0, 0);
    for (int i = beg; i < end; i++) {
        int2 cur = es;
        if (i + 1 < end) es = g_elist[i + 1];
        float a = 0.f;
        if (lane < 8) {
            float wl = out_attn[(size_t)cur.x * HH + lane];
            a = wl * inv_h;
            out_attn[(size_t)cur.x * HH + lane] = a;
        }
        float ah = __shfl_sync(FULL, a, lane >> 2);
        uint2 hv = *(const uint2*)(g_vh + (size_t)cur.y * DM + lane * 4);
        float2 v01 = __half22float2(*(__half2*)&hv.x);
        float2 v23 = __half22float2(*(__half2*)&hv.y);
        acc.x += v01.x * ah;
        acc.y += v01.y * ah;
        acc.z += v23.x * ah;
        acc.w += v23.y * ah;
    }

    *(float4*)(out_states + (size_t)nd * DM + lane * 4) = acc;
}

// ---------------- launch ----------------
extern "C" void kernel_launch(void* const* d_in, const int* in_sizes, int n_in,
                              void* d_out, int out_size)
{
    const float* x   = (const float*)d_in[0];
    const float* pi  = (const float*)d_in[1];
    const float* vw  = (const float*)d_in[2];
    const float* Wq  = (const float*)d_in[3];
    const float* bq  = (const float*)d_in[4];
    const float* Wk  = (const float*)d_in[5];
    const float* bk  = (const float*)d_in[6];
    const float* Wv  = (const float*)d_in[7];
    const float* bv  = (const float*)d_in[8];
    const int*   src = (const int*)d_in[9];
    const int*   dst = (const int*)d_in[10];

    const int n = in_sizes[0] / DM;    // nodes
    const int e = in_sizes[10];        // edges

    float* out  = (float*)d_out;
    float* attn = out + (size_t)n * DM;

    int gb = (e + 255) / 256;
    if (gb > 4096) gb = 4096;

    const int nb = (n + 1023) / 1024;  // scan blocks (<=128)

    // QKV projection (independent of CSR build)
    qkv_kernel<<<(n + 31) / 32, 256>>>(x, Wq, bq, Wk, bk, Wv, bv, n);

    // CSR by dst (parallel 3-phase scan)
    zero_count_kernel<<<(n + 255) / 256, 256>>>(n);
    hist_kernel<<<gb, 256>>>(dst, e);
    blockscan_kernel<<<nb, 1024>>>(n);
    bsumscan_kernel<<<1, 32>>>(nb, n);
    addoff_kernel<<<(n + 255) / 256, 256>>>(n);
    scatter_kernel<<<gb, 256>>>(src, dst, e);

    // fused scores + softmax + aggregation
    node_kernel<<<(n + 7) / 8, 256>>>(pi, vw, out, attn, n);
}

// round 5
// speedup vs baseline: 1.3089x; 1.0551x over previous
#include <cuda_runtime.h>
#include <cuda_fp16.h>
#include <cstdint>

// Problem constants (fixed instance)
#define DM   128      // model dim
#define HH   8        // heads
#define DHD  16       // head dim
#define MV   3        // views
#define MAXN 100000
#define MAXE 1600000

typedef unsigned long long ull;

// ---------------- scratch (static __device__ — no allocations) ----------------
__device__ float  g_q[(size_t)MAXN * DM];
__device__ float  g_k[(size_t)MAXN * DM];
__device__ __half g_vh[(size_t)MAXN * DM];   // V stored fp16 (read-only gather)
__device__ float  g_inv[(size_t)MAXN * HH];  // per (node, head) 1/sum
__device__ int    g_count[MAXN];
__device__ int    g_rowptr[MAXN + 1];
__device__ int    g_rowfill[MAXN];
__device__ int    g_bsum[128];
__device__ int    g_boff[128];
__device__ int2   g_elist[MAXE];             // (edge_id, src)

// ---------------- packed f32x2 helpers ----------------
__device__ __forceinline__ ull fma2(ull a, ull b, ull c) {
    ull d;
    asm("fma.rn.f32x2 %0, %1, %2, %3;" : "=l"(d) : "l"(a), "l"(b), "l"(c));
    return d;
}
__device__ __forceinline__ ull bcast2(float x) {
    ull d;
    asm("mov.b64 %0, {%1, %1};" : "=l"(d) : "r"(__float_as_uint(x)));
    return d;
}

// ---------------- CSR build ----------------
__global__ void zero_count_kernel(int n) {
    int i = blockIdx.x * blockDim.x + threadIdx.x;
    if (i < n) g_count[i] = 0;
}

__global__ void hist_kernel(const int* __restrict__ dst, int e) {
    for (int i = blockIdx.x * blockDim.x + threadIdx.x; i < e; i += gridDim.x * blockDim.x)
        atomicAdd(&g_count[dst[i]], 1);
}

// per-1024-chunk exclusive scan; block totals to g_bsum
__global__ __launch_bounds__(1024) void blockscan_kernel(int n) {
    __shared__ int s_wsum[32];
    const int tid = threadIdx.x;
    const int lane = tid & 31, wid = tid >> 5;
    const int i = blockIdx.x * 1024 + tid;
    int v = (i < n) ? g_count[i] : 0;
    int x = v;
#pragma unroll
    for (int o = 1; o < 32; o <<= 1) {
        int t = __shfl_up_sync(0xffffffffu, x, o);
        if (lane >= o) x += t;
    }
    if (lane == 31) s_wsum[wid] = x;
    __syncthreads();
    if (wid == 0) {
        int ws = s_wsum[lane];
#pragma unroll
        for (int o = 1; o < 32; o <<= 1) {
            int t = __shfl_up_sync(0xffffffffu, ws, o);
            if (lane >= o) ws += t;
        }
        s_wsum[lane] = ws;
    }
    __syncthreads();
    int excl = (wid ? s_wsum[wid - 1] : 0) + (x - v);
    if (i < n) g_rowptr[i] = excl;
    if (tid == 0) g_bsum[blockIdx.x] = s_wsum[31];
}

// scan the (<=128) block totals on one warp; writes rowptr[n]
__global__ void bsumscan_kernel(int nb, int n) {
    const int lane = threadIdx.x;
    int carry = 0;
    for (int base = 0; base < nb; base += 32) {
        int idx = base + lane;
        int v = (idx < nb) ? g_bsum[idx] : 0;
        int x = v;
#pragma unroll
        for (int o = 1; o < 32; o <<= 1) {
            int t = __shfl_up_sync(0xffffffffu, x, o);
            if (lane >= o) x += t;
        }
        if (idx < nb) g_boff[idx] = carry + (x - v);
        carry += __shfl_sync(0xffffffffu, x, 31);
    }
    if (lane == 0) g_rowptr[n] = carry;
}

__global__ void addoff_kernel(int n) {
    int i = blockIdx.x * blockDim.x + threadIdx.x;
    if (i < n) {
        int r = g_rowptr[i] + g_boff[i >> 10];
        g_rowptr[i] = r;
        g_rowfill[i] = r;
    }
}

__global__ void scatter_kernel(const int* __restrict__ src, const int* __restrict__ dst, int e) {
    for (int i = blockIdx.x * blockDim.x + threadIdx.x; i < e; i += gridDim.x * blockDim.x) {
        int d = dst[i];
        int pos = atomicAdd(&g_rowfill[d], 1);
        g_elist[pos] = make_int2(i, src[i]);
    }
}

// ---------------- fused QKV projection (fp32 math, packed f32x2 FMA) ----------------
__global__ __launch_bounds__(256) void qkv_kernel(
    const float* __restrict__ x,
    const float* __restrict__ Wq, const float* __restrict__ bqv,
    const float* __restrict__ Wk, const float* __restrict__ bkv,
    const float* __restrict__ Wv, const float* __restrict__ bvv,
    int n)
{
    __shared__ float sx[32][DM];  // 16KB
    const int row0 = blockIdx.x * 32;

    for (int t = threadIdx.x; t < 32 * 32; t += 256) {
        int r = t >> 5, c4 = t & 31;
        int row = row0 + r;
        float4 xv = make_float4(0.f, 0.f, 0.f, 0.f);
        if (row < n) xv = *(const float4*)(x + (size_t)row * DM + c4 * 4);
        *(float4*)(&sx[r][c4 * 4]) = xv;
    }
    __syncthreads();

    const int cp = threadIdx.x & 63;
    const int rg = threadIdx.x >> 6;
    const int c  = cp * 2;

    const ull* wq8 = reinterpret_cast<const ull*>(Wq) + cp;
    const ull* wk8 = reinterpret_cast<const ull*>(Wk) + cp;
    const ull* wv8 = reinterpret_cast<const ull*>(Wv) + cp;

    ull bq2 = reinterpret_cast<const ull*>(bqv)[cp];
    ull bk2 = reinterpret_cast<const ull*>(bkv)[cp];
    ull bv2 = reinterpret_cast<const ull*>(bvv)[cp];

    ull aq[8], ak[8], av[8];
#pragma unroll
    for (int r = 0; r < 8; r++) { aq[r] = bq2; ak[r] = bk2; av[r] = bv2; }

#pragma unroll 8
    for (int d = 0; d < DM; d++) {
        ull wq = wq8[(size_t)d * 64];
        ull wk = wk8[(size_t)d * 64];
        ull wv = wv8[(size_t)d * 64];
#pragma unroll
        for (int r = 0; r < 8; r++) {
            ull x2 = bcast2(sx[rg * 8 + r][d]);
            aq[r] = fma2(x2, wq, aq[r]);
            ak[r] = fma2(x2, wk, ak[r]);
            av[r] = fma2(x2, wv, av[r]);
        }
    }

#pragma unroll
    for (int r = 0; r < 8; r++) {
        int row = row0 + rg * 8 + r;
        if (row < n) {
            *(ull*)(g_q + (size_t)row * DM + c) = aq[r];
            *(ull*)(g_k + (size_t)row * DM + c) = ak[r];
            float2 vf;
            vf.x = __uint_as_float((unsigned)(av[r] & 0xffffffffu));
            vf.y = __uint_as_float((unsigned)(av[r] >> 32));
            *(__half2*)(g_vh + (size_t)row * DM + c) = __float22half2_rn(vf);
        }
    }
}

// ---------------- single-pass node kernel: scores + weights + aggregation ----------------
// One warp per node. Lane l owns features [4l,4l+4), head h = l>>2.
// Accumulates unnormalized Σw·v and Σw in one loop; writes unnormalized w to out_attn,
// per-(node,head) 1/Σw to g_inv (normalized later by an edge-parallel kernel).
__global__ __launch_bounds__(256) void node_kernel(
    const float* __restrict__ pi,
    const float* __restrict__ view_w,
    float* __restrict__ out_states,   // [N, 128]
    float* __restrict__ out_attn,     // [E, 8] (unnormalized here)
    int n)
{
    const int nd = blockIdx.x * (blockDim.x >> 5) + (threadIdx.x >> 5);
    if (nd >= n) return;
    const int lane = threadIdx.x & 31;
    const unsigned FULL = 0xffffffffu;

    const int beg = g_rowptr[nd];
    const int end = g_rowptr[nd + 1];

    const float4 qv = *(const float4*)(g_q + (size_t)nd * DM + lane * 4);
    const int h = lane >> 2;
    const float* pip = pi + (size_t)nd * (HH * MV) + h * MV;
    const float pi0 = pip[0], pi1 = pip[1], pi2 = pip[2];

    float ssum = 0.f;
    float4 acc = make_float4(0.f, 0.f, 0.f, 0.f);

    // software pipeline: prefetch elist 2 ahead
    int2 e0 = (beg < end)     ? g_elist[beg]     : make_int2(0, 0);
    int2 e1 = (beg + 1 < end) ? g_elist[beg + 1] : make_int2(0, 0);

    for (int i = beg; i < end; i++) {
        const int2 cur = e0;
        e0 = e1;
        if (i + 2 < end) e1 = g_elist[i + 2];

        // independent gathers (2x MLP): k row + v row of source node
        const float4 kv = *(const float4*)(g_k + (size_t)cur.y * DM + lane * 4);
        const uint2 hv = *(const uint2*)(g_vh + (size_t)cur.y * DM + lane * 4);
        const float* vw = view_w + (size_t)cur.x * MV;
        const float mix = pi0 * vw[0] + pi1 * vw[1] + pi2 * vw[2];

        float p = qv.x * kv.x + qv.y * kv.y + qv.z * kv.z + qv.w * kv.w;
        p += __shfl_xor_sync(FULL, p, 1);
        p += __shfl_xor_sync(FULL, p, 2);      // head dot replicated in 4-lane group
        const float w = (mix > 0.f) ? __expf(p * 0.25f) * fmaxf(mix, 1e-8f) : 0.f;
        ssum += w;                              // replicated within group

        const float wl = __shfl_sync(FULL, w, (lane & 7) * 4);
        if (lane < 8) out_attn[(size_t)cur.x * HH + lane] = wl;

        // accumulate with per-lane (head-replicated) weight
        const float2 v01 = __half22float2(*(const __half2*)&hv.x);
        const float2 v23 = __half22float2(*(const __half2*)&hv.y);
        acc.x += v01.x * w;
        acc.y += v01.y * w;
        acc.z += v23.x * w;
        acc.w += v23.y * w;
    }

    const float inv = 1.f / fmaxf(ssum, 1e-8f);
    acc.x *= inv; acc.y *= inv; acc.z *= inv; acc.w *= inv;
    *(float4*)(out_states + (size_t)nd * DM + lane * 4) = acc;

    const float inv_h = __shfl_sync(FULL, inv, lane * 4);  // valid for lane<8
    if (lane < 8) g_inv[(size_t)nd * HH + lane] = inv_h;
}

// ---------------- edge-parallel attn normalization ----------------
// attn[e][h] *= inv[dst[e]][h]; one thread per edge, float4 x2.
__global__ __launch_bounds__(256) void normalize_kernel(
    const int* __restrict__ dst,
    float* __restrict__ out_attn,
    int e)
{
    const int i = blockIdx.x * blockDim.x + threadIdx.x;
    if (i >= e) return;
    const int d = dst[i];
    const float4 i0 = *(const float4*)(g_inv + (size_t)d * HH);
    const float4 i1 = *(const float4*)(g_inv + (size_t)d * HH + 4);
    float4 a0 = *(const float4*)(out_attn + (size_t)i * HH);
    float4 a1 = *(const float4*)(out_attn + (size_t)i * HH + 4);
    a0.x *= i0.x; a0.y *= i0.y; a0.z *= i0.z; a0.w *= i0.w;
    a1.x *= i1.x; a1.y *= i1.y; a1.z *= i1.z; a1.w *= i1.w;
    *(float4*)(out_attn + (size_t)i * HH)     = a0;
    *(float4*)(out_attn + (size_t)i * HH + 4) = a1;
}

// ---------------- launch ----------------
extern "C" void kernel_launch(void* const* d_in, const int* in_sizes, int n_in,
                              void* d_out, int out_size)
{
    const float* x   = (const float*)d_in[0];
    const float* pi  = (const float*)d_in[1];
    const float* vw  = (const float*)d_in[2];
    const float* Wq  = (const float*)d_in[3];
    const float* bq  = (const float*)d_in[4];
    const float* Wk  = (const float*)d_in[5];
    const float* bk  = (const float*)d_in[6];
    const float* Wv  = (const float*)d_in[7];
    const float* bv  = (const float*)d_in[8];
    const int*   src = (const int*)d_in[9];
    const int*   dst = (const int*)d_in[10];

    const int n = in_sizes[0] / DM;    // nodes
    const int e = in_sizes[10];        // edges

    float* out  = (float*)d_out;
    float* attn = out + (size_t)n * DM;

    int gb = (e + 255) / 256;
    if (gb > 4096) gb = 4096;

    const int nb = (n + 1023) / 1024;  // scan blocks (<=128)

    // QKV projection (independent of CSR build)
    qkv_kernel<<<(n + 31) / 32, 256>>>(x, Wq, bq, Wk, bk, Wv, bv, n);

    // CSR by dst (parallel 3-phase scan)
    zero_count_kernel<<<(n + 255) / 256, 256>>>(n);
    hist_kernel<<<gb, 256>>>(dst, e);
    blockscan_kernel<<<nb, 1024>>>(n);
    bsumscan_kernel<<<1, 32>>>(nb, n);
    addoff_kernel<<<(n + 255) / 256, 256>>>(n);
    scatter_kernel<<<gb, 256>>>(src, dst, e);

    // single-pass fused scores + softmax + aggregation
    node_kernel<<<(n + 7) / 8, 256>>>(pi, vw, out, attn, n);

    // edge-parallel attn normalization
    normalize_kernel<<<(e + 255) / 256, 256>>>(dst, attn, e);
}